// round 5
// baseline (speedup 1.0000x reference)
#include <cuda_runtime.h>
#include <cuda_bf16.h>

#define N_MOLS        2000
#define ATOMS_PER_MOL 50
#define N_ATOMS       (N_MOLS * ATOMS_PER_MOL + 1)   // 100001
#define N_BONDS       200001
#define MAX_NB        6
#define ATOM_FDIM     133
#define BOND_FDIM     147
#define HIDDEN        300
#define DEPTH         4

// ---------------- persistent scratch (device globals; no runtime alloc) ----------------
__device__ float g_inp [(size_t)N_BONDS * HIDDEN];   // f_bonds @ W_i (pre-relu)
__device__ float g_msg [(size_t)N_BONDS * HIDDEN];   // current message
__device__ float g_tmp [(size_t)N_BONDS * HIDDEN];   // pre-GEMM bond message
__device__ float g_amsg[(size_t)N_ATOMS * HIDDEN];   // per-atom aggregated message
__device__ float g_ah  [(size_t)N_ATOMS * HIDDEN];   // atom hiddens

// ---------------- fp32 tiled GEMM, N fixed = HIDDEN = 300 ----------------
// C[M,300] = relu?( A[M,K] @ B[K,300] (+ addsrc) (+ bias) ); optional pre-relu store.
#define BM 128
#define BN 64
#define BKT 16

__global__ __launch_bounds__(256) void sgemm300(
    const float* __restrict__ A, int lda,
    const float* __restrict__ B,          // [K,300] row-major
    float* __restrict__ C,                // [M,300]
    const float* __restrict__ addsrc,     // [M,300] or null
    const float* __restrict__ bias,       // [300] or null
    float* __restrict__ rawout,           // [M,300] or null (stores pre-relu value)
    int M, int K, int doRelu)
{
    __shared__ __align__(16) float As[BKT][BM + 4];  // row = 132 floats (16B-aligned rows)
    __shared__ __align__(16) float Bs[BKT][BN + 4];  // row = 68 floats

    const int tid = threadIdx.x;
    const int tx = tid & 15;          // 0..15 -> 4 cols each
    const int ty = tid >> 4;          // 0..15 -> 8 rows each
    const int rowBlock = blockIdx.y * BM;
    const int colBlock = blockIdx.x * BN;

    const int a_k  = tid & 15;        // k within tile
    const int a_m0 = tid >> 4;        // row (+16*i)
    const int b_n  = tid & 63;        // col within tile
    const int b_k0 = tid >> 6;        // k (+4*i)

    float acc[8][4];
    #pragma unroll
    for (int i = 0; i < 8; i++)
        #pragma unroll
        for (int j = 0; j < 4; j++) acc[i][j] = 0.f;

    for (int k0 = 0; k0 < K; k0 += BKT) {
        #pragma unroll
        for (int i = 0; i < 8; i++) {
            int m  = a_m0 + 16 * i;
            int gr = rowBlock + m;
            int gk = k0 + a_k;
            As[a_k][m] = (gr < M && gk < K) ? A[(size_t)gr * lda + gk] : 0.f;
        }
        #pragma unroll
        for (int i = 0; i < 4; i++) {
            int kk = b_k0 + 4 * i;
            int gk = k0 + kk;
            int gn = colBlock + b_n;
            Bs[kk][b_n] = (gk < K && gn < HIDDEN) ? B[(size_t)gk * HIDDEN + gn] : 0.f;
        }
        __syncthreads();

        #pragma unroll
        for (int kk = 0; kk < BKT; kk++) {
            float4 a0 = *reinterpret_cast<const float4*>(&As[kk][ty * 8]);
            float4 a1 = *reinterpret_cast<const float4*>(&As[kk][ty * 8 + 4]);
            float4 bv = *reinterpret_cast<const float4*>(&Bs[kk][tx * 4]);
            float ar[8] = {a0.x, a0.y, a0.z, a0.w, a1.x, a1.y, a1.z, a1.w};
            float br[4] = {bv.x, bv.y, bv.z, bv.w};
            #pragma unroll
            for (int i = 0; i < 8; i++)
                #pragma unroll
                for (int j = 0; j < 4; j++)
                    acc[i][j] = fmaf(ar[i], br[j], acc[i][j]);
        }
        __syncthreads();
    }

    #pragma unroll
    for (int i = 0; i < 8; i++) {
        int row = rowBlock + ty * 8 + i;
        if (row >= M) continue;
        #pragma unroll
        for (int j = 0; j < 4; j++) {
            int col = colBlock + tx * 4 + j;
            if (col >= HIDDEN) continue;
            float v = acc[i][j];
            if (bias)   v += bias[col];
            if (addsrc) v += addsrc[(size_t)row * HIDDEN + col];
            if (rawout) rawout[(size_t)row * HIDDEN + col] = v;
            C[(size_t)row * HIDDEN + col] = doRelu ? fmaxf(v, 0.f) : v;
        }
    }
}

// ---------------- atom aggregation: amsg[a] = sum_k w_bonds[a2b[a,k]] * msg[a2b[a,k]] ----------------
__global__ __launch_bounds__(320) void gather_atoms(
    const float* __restrict__ msg, const float* __restrict__ w_bonds,
    const int* __restrict__ a2b, float* __restrict__ amsg)
{
    const int a = blockIdx.x;
    const int c = threadIdx.x;
    __shared__ int   sb[MAX_NB];
    __shared__ float sw[MAX_NB];
    if (c < MAX_NB) {
        int b = a2b[(size_t)a * MAX_NB + c];
        sb[c] = b;
        sw[c] = w_bonds[b];
    }
    __syncthreads();
    if (c < HIDDEN) {
        float acc = 0.f;
        #pragma unroll
        for (int k = 0; k < MAX_NB; k++)
            acc = fmaf(sw[k], msg[(size_t)sb[k] * HIDDEN + c], acc);
        amsg[(size_t)a * HIDDEN + c] = acc;
    }
}

// ---------------- bond update: tmp[b] = amsg[b2a[b]] - w_bonds[b] * msg[b2revb[b]] ----------------
__global__ __launch_bounds__(320) void bond_update(
    const float* __restrict__ amsg, const float* __restrict__ msg,
    const float* __restrict__ w_bonds,
    const int* __restrict__ b2a, const int* __restrict__ b2revb,
    float* __restrict__ tmp)
{
    const int b = blockIdx.x;
    const int c = threadIdx.x;
    __shared__ int   sa, srb;
    __shared__ float sw;
    if (c == 0) { sa = b2a[b]; srb = b2revb[b]; sw = w_bonds[b]; }
    __syncthreads();
    if (c < HIDDEN) {
        float v = amsg[(size_t)sa * HIDDEN + c] - sw * msg[(size_t)srb * HIDDEN + c];
        tmp[(size_t)b * HIDDEN + c] = v;
    }
}

// ---------------- readout: out[m] = dop[m] * sum_a(w*ah) / sum_a(w), 50 atoms per molecule ----------------
__global__ __launch_bounds__(320) void readout(
    const float* __restrict__ ah, const float* __restrict__ w_atoms,
    const float* __restrict__ dop, float* __restrict__ out)
{
    const int m = blockIdx.x;
    const int c = threadIdx.x;
    if (c >= HIDDEN) return;
    const int base = 1 + m * ATOMS_PER_MOL;   // atom 0 is the padding row (dropped)
    float s = 0.f, ws = 0.f;
    #pragma unroll 5
    for (int i = 0; i < ATOMS_PER_MOL; i++) {
        float w = w_atoms[base + i];
        ws += w;
        s = fmaf(w, ah[(size_t)(base + i) * HIDDEN + c], s);
    }
    out[(size_t)m * HIDDEN + c] = dop[m] * (s / ws);
}

// ---------------- launch ----------------
extern "C" void kernel_launch(void* const* d_in, const int* in_sizes, int n_in,
                              void* d_out, int out_size)
{
    const float* f_atoms = (const float*)d_in[0];
    const float* f_bonds = (const float*)d_in[1];
    const float* w_atoms = (const float*)d_in[2];
    const float* w_bonds = (const float*)d_in[3];
    const float* dop     = (const float*)d_in[4];
    const float* W_i     = (const float*)d_in[5];
    const float* W_h     = (const float*)d_in[6];
    const float* W_o     = (const float*)d_in[7];
    const float* b_o     = (const float*)d_in[8];
    const int*   a2b     = (const int*)d_in[9];
    const int*   b2a     = (const int*)d_in[10];
    const int*   b2revb  = (const int*)d_in[11];
    float* out = (float*)d_out;

    float *inp, *msg, *tmp, *amsg, *ah;
    cudaGetSymbolAddress((void**)&inp,  g_inp);
    cudaGetSymbolAddress((void**)&msg,  g_msg);
    cudaGetSymbolAddress((void**)&tmp,  g_tmp);
    cudaGetSymbolAddress((void**)&amsg, g_amsg);
    cudaGetSymbolAddress((void**)&ah,   g_ah);

    dim3 blk(256);
    dim3 gridBonds((HIDDEN + BN - 1) / BN, (N_BONDS + BM - 1) / BM);   // (5, 1563)
    dim3 gridAtoms((HIDDEN + BN - 1) / BN, (N_ATOMS + BM - 1) / BM);   // (5, 782)

    // inp = f_bonds @ W_i ; msg = relu(inp)
    sgemm300<<<gridBonds, blk>>>(f_bonds, BOND_FDIM, W_i, msg,
                                 nullptr, nullptr, inp, N_BONDS, BOND_FDIM, 1);

    for (int d = 0; d < DEPTH - 1; ++d) {
        gather_atoms<<<N_ATOMS, 320>>>(msg, w_bonds, a2b, amsg);
        bond_update<<<N_BONDS, 320>>>(amsg, msg, w_bonds, b2a, b2revb, tmp);
        // msg = relu(inp + tmp @ W_h)
        sgemm300<<<gridBonds, blk>>>(tmp, HIDDEN, W_h, msg,
                                     inp, nullptr, nullptr, N_BONDS, HIDDEN, 1);
    }

    gather_atoms<<<N_ATOMS, 320>>>(msg, w_bonds, a2b, amsg);

    // ah = f_atoms @ W_o[0:133] + b_o   (no relu yet)
    sgemm300<<<gridAtoms, blk>>>(f_atoms, ATOM_FDIM, W_o, ah,
                                 nullptr, b_o, nullptr, N_ATOMS, ATOM_FDIM, 0);
    // ah = relu(ah + amsg @ W_o[133:433])
    sgemm300<<<gridAtoms, blk>>>(amsg, HIDDEN, W_o + (size_t)ATOM_FDIM * HIDDEN, ah,
                                 ah, nullptr, nullptr, N_ATOMS, HIDDEN, 1);

    readout<<<N_MOLS, 320>>>(ah, w_atoms, dop, out);
}

// round 6
// speedup vs baseline: 1.7442x; 1.7442x over previous
#include <cuda_runtime.h>
#include <cuda_bf16.h>
#include <cstdint>

#define N_MOLS        2000
#define ATOMS_PER_MOL 50
#define N_ATOMS       (N_MOLS * ATOMS_PER_MOL + 1)   // 100001
#define N_BONDS       200001
#define MAX_NB        6
#define ATOM_FDIM     133
#define BOND_FDIM     147
#define HIDDEN        300
#define DEPTH         4
#define H4            (HIDDEN / 4)                   // 75 float4 per row

// ---------------- persistent scratch (device globals; no runtime alloc) ----------------
__device__ float g_inp [(size_t)N_BONDS * HIDDEN];   // f_bonds @ W_i (pre-relu)
__device__ float g_msg [(size_t)N_BONDS * HIDDEN];   // current message
__device__ float g_tmp [(size_t)N_BONDS * HIDDEN];   // pre-GEMM bond message
__device__ float g_amsg[(size_t)N_ATOMS * HIDDEN];   // per-atom aggregated message
__device__ float g_ah  [(size_t)N_ATOMS * HIDDEN];   // atom hiddens

// ---------------- tf32 helpers ----------------
__device__ __forceinline__ uint32_t f2tf(float x) {
    uint32_t u;
    asm("cvt.rna.tf32.f32 %0, %1;" : "=r"(u) : "f"(x));
    return u;
}

__device__ __forceinline__ void mma_tf32(float* c, const uint32_t* a, const uint32_t* b) {
    asm volatile(
        "mma.sync.aligned.m16n8k8.row.col.f32.tf32.tf32.f32 "
        "{%0,%1,%2,%3}, {%4,%5,%6,%7}, {%8,%9}, {%0,%1,%2,%3};"
        : "+f"(c[0]), "+f"(c[1]), "+f"(c[2]), "+f"(c[3])
        : "r"(a[0]), "r"(a[1]), "r"(a[2]), "r"(a[3]), "r"(b[0]), "r"(b[1]));
}

// ---------------- tf32 tensor-core GEMM, N fixed = 300 (tiled as 4 x 80) ----------------
// C[M,300] = relu?( A[M,K] @ B[K,300] (+ addsrc) (+ bias) ); optional pre-relu store.
#define TBM 128
#define TBN 80
#define TBK 16
#define ASTRIDE 20    // conflict-free for A-fragment lane pattern
#define BSTRIDE 88    // conflict-free for B-fragment lane pattern

__global__ __launch_bounds__(256) void tgemm300(
    const float* __restrict__ A, int lda,
    const float* __restrict__ B,          // [K,300] row-major
    float* __restrict__ C,                // [M,300]
    const float* __restrict__ addsrc,     // [M,300] or null
    const float* __restrict__ bias,       // [300] or null
    float* __restrict__ rawout,           // [M,300] or null (pre-relu value)
    int M, int K, int doRelu)
{
    __shared__ uint32_t As[TBM][ASTRIDE];     // [m][k], tf32 bits
    __shared__ uint32_t Bs[TBK][BSTRIDE];     // [k][n], tf32 bits

    const int tid  = threadIdx.x;
    const int lane = tid & 31;
    const int warp = tid >> 5;
    const int g = lane >> 2;      // 0..7
    const int t = lane & 3;       // 0..3
    const int warpM = warp & 3;   // 4 warps along M
    const int warpN = warp >> 2;  // 2 warps along N
    const int m0w = warpM * 32;
    const int n0w = warpN * 40;

    const int rowBase = blockIdx.y * TBM;
    const int colBase = blockIdx.x * TBN;

    // A staging: thread -> row am, 8 consecutive k starting at ak
    const int am = tid >> 1;            // 0..127
    const int ak = (tid & 1) * 8;       // 0 or 8

    float acc[2][5][4];
    #pragma unroll
    for (int i = 0; i < 2; i++)
        #pragma unroll
        for (int j = 0; j < 5; j++)
            #pragma unroll
            for (int q = 0; q < 4; q++) acc[i][j][q] = 0.f;

    float aReg[8];
    float bReg[5];
    const int gr = rowBase + am;
    const bool vec = ((lda & 3) == 0);

    auto loadA = [&](int k0) {
        if (gr < M) {
            if (vec) {
                #pragma unroll
                for (int jj = 0; jj < 8; jj += 4) {
                    int gk = k0 + ak + jj;
                    if (gk + 3 < K) {
                        float4 v = *reinterpret_cast<const float4*>(A + (size_t)gr * lda + gk);
                        aReg[jj] = v.x; aReg[jj+1] = v.y; aReg[jj+2] = v.z; aReg[jj+3] = v.w;
                    } else {
                        #pragma unroll
                        for (int j = 0; j < 4; j++) {
                            int k = gk + j;
                            aReg[jj + j] = (k < K) ? A[(size_t)gr * lda + k] : 0.f;
                        }
                    }
                }
            } else {
                #pragma unroll
                for (int j = 0; j < 8; j++) {
                    int gk = k0 + ak + j;
                    aReg[j] = (gk < K) ? A[(size_t)gr * lda + gk] : 0.f;
                }
            }
        } else {
            #pragma unroll
            for (int j = 0; j < 8; j++) aReg[j] = 0.f;
        }
    };
    auto loadB = [&](int k0) {
        #pragma unroll
        for (int i = 0; i < 5; i++) {
            int e  = i * 256 + tid;      // [0,1280)
            int bk = e / TBN;
            int bn = e % TBN;
            int gk = k0 + bk;
            int gn = colBase + bn;
            bReg[i] = (gk < K && gn < HIDDEN) ? B[(size_t)gk * HIDDEN + gn] : 0.f;
        }
    };

    const int nChunks = (K + TBK - 1) / TBK;
    loadA(0); loadB(0);

    for (int c = 0; c < nChunks; c++) {
        #pragma unroll
        for (int j = 0; j < 8; j++) As[am][ak + j] = f2tf(aReg[j]);
        #pragma unroll
        for (int i = 0; i < 5; i++) {
            int e = i * 256 + tid;
            Bs[e / TBN][e % TBN] = f2tf(bReg[i]);
        }
        __syncthreads();

        if (c + 1 < nChunks) { loadA((c + 1) * TBK); loadB((c + 1) * TBK); }

        #pragma unroll
        for (int kk = 0; kk < TBK; kk += 8) {
            uint32_t af[2][4];
            #pragma unroll
            for (int mt = 0; mt < 2; mt++) {
                int mr = m0w + mt * 16;
                af[mt][0] = As[mr + g    ][kk + t    ];
                af[mt][1] = As[mr + g + 8][kk + t    ];
                af[mt][2] = As[mr + g    ][kk + t + 4];
                af[mt][3] = As[mr + g + 8][kk + t + 4];
            }
            uint32_t bf[5][2];
            #pragma unroll
            for (int nt = 0; nt < 5; nt++) {
                int nc = n0w + nt * 8 + g;
                bf[nt][0] = Bs[kk + t    ][nc];
                bf[nt][1] = Bs[kk + t + 4][nc];
            }
            #pragma unroll
            for (int mt = 0; mt < 2; mt++)
                #pragma unroll
                for (int nt = 0; nt < 5; nt++)
                    mma_tf32(acc[mt][nt], af[mt], bf[nt]);
        }
        __syncthreads();
    }

    // epilogue
    #pragma unroll
    for (int mt = 0; mt < 2; mt++) {
        int r0 = rowBase + m0w + mt * 16 + g;
        int r1 = r0 + 8;
        #pragma unroll
        for (int nt = 0; nt < 5; nt++) {
            int c0 = colBase + n0w + nt * 8 + t * 2;
            #pragma unroll
            for (int q = 0; q < 4; q++) {
                int row = (q < 2) ? r0 : r1;
                int col = c0 + (q & 1);
                if (row >= M || col >= HIDDEN) continue;
                float v = acc[mt][nt][q];
                if (bias)   v += bias[col];
                if (addsrc) v += addsrc[(size_t)row * HIDDEN + col];
                if (rawout) rawout[(size_t)row * HIDDEN + col] = v;
                C[(size_t)row * HIDDEN + col] = doRelu ? fmaxf(v, 0.f) : v;
            }
        }
    }
}

// ---------------- atom aggregation (float4): amsg[a] = sum_k w[a2b[a,k]] * msg[a2b[a,k]] ----------------
__global__ __launch_bounds__(320) void gather_atoms4(
    const float4* __restrict__ msg4, const float* __restrict__ w_bonds,
    const int* __restrict__ a2b, float4* __restrict__ amsg4)
{
    const int tx = threadIdx.x;        // 0..79
    const int ty = threadIdx.y;        // 0..3
    const int a  = blockIdx.x * 4 + ty;
    __shared__ int   sb[4][MAX_NB];
    __shared__ float sw[4][MAX_NB];
    if (a < N_ATOMS && tx < MAX_NB) {
        int b = a2b[(size_t)a * MAX_NB + tx];
        sb[ty][tx] = b;
        sw[ty][tx] = w_bonds[b];
    }
    __syncthreads();
    if (a < N_ATOMS && tx < H4) {
        float4 acc = make_float4(0.f, 0.f, 0.f, 0.f);
        #pragma unroll
        for (int k = 0; k < MAX_NB; k++) {
            float  w = sw[ty][k];
            float4 v = msg4[(size_t)sb[ty][k] * H4 + tx];
            acc.x = fmaf(w, v.x, acc.x);
            acc.y = fmaf(w, v.y, acc.y);
            acc.z = fmaf(w, v.z, acc.z);
            acc.w = fmaf(w, v.w, acc.w);
        }
        amsg4[(size_t)a * H4 + tx] = acc;
    }
}

// ---------------- bond update (float4): tmp[b] = amsg[b2a[b]] - w_bonds[b]*msg[b2revb[b]] ----------------
__global__ __launch_bounds__(320) void bond_update4(
    const float4* __restrict__ amsg4, const float4* __restrict__ msg4,
    const float* __restrict__ w_bonds,
    const int* __restrict__ b2a, const int* __restrict__ b2revb,
    float4* __restrict__ tmp4)
{
    const int tx = threadIdx.x;
    const int ty = threadIdx.y;
    const int b  = blockIdx.x * 4 + ty;
    __shared__ int   sa[4], srb[4];
    __shared__ float sw[4];
    if (b < N_BONDS && tx == 0) { sa[ty] = b2a[b]; srb[ty] = b2revb[b]; sw[ty] = w_bonds[b]; }
    __syncthreads();
    if (b < N_BONDS && tx < H4) {
        float4 am = amsg4[(size_t)sa[ty]  * H4 + tx];
        float4 mv = msg4 [(size_t)srb[ty] * H4 + tx];
        float  w  = sw[ty];
        float4 o;
        o.x = am.x - w * mv.x;
        o.y = am.y - w * mv.y;
        o.z = am.z - w * mv.z;
        o.w = am.w - w * mv.w;
        tmp4[(size_t)b * H4 + tx] = o;
    }
}

// ---------------- readout (float4): out[m] = dop[m] * sum(w*ah) / sum(w) ----------------
__global__ __launch_bounds__(320) void readout4(
    const float4* __restrict__ ah4, const float* __restrict__ w_atoms,
    const float* __restrict__ dop, float4* __restrict__ out4)
{
    const int tx = threadIdx.x;
    const int ty = threadIdx.y;
    const int m  = blockIdx.x * 4 + ty;
    if (m >= N_MOLS || tx >= H4) return;
    const int base = 1 + m * ATOMS_PER_MOL;   // atom 0 is padding (dropped)
    float4 s = make_float4(0.f, 0.f, 0.f, 0.f);
    float ws = 0.f;
    #pragma unroll 5
    for (int i = 0; i < ATOMS_PER_MOL; i++) {
        float  w = w_atoms[base + i];
        float4 v = ah4[(size_t)(base + i) * H4 + tx];
        ws += w;
        s.x = fmaf(w, v.x, s.x);
        s.y = fmaf(w, v.y, s.y);
        s.z = fmaf(w, v.z, s.z);
        s.w = fmaf(w, v.w, s.w);
    }
    float sc = dop[m] / ws;
    s.x *= sc; s.y *= sc; s.z *= sc; s.w *= sc;
    out4[(size_t)m * H4 + tx] = s;
}

// ---------------- launch ----------------
extern "C" void kernel_launch(void* const* d_in, const int* in_sizes, int n_in,
                              void* d_out, int out_size)
{
    const float* f_atoms = (const float*)d_in[0];
    const float* f_bonds = (const float*)d_in[1];
    const float* w_atoms = (const float*)d_in[2];
    const float* w_bonds = (const float*)d_in[3];
    const float* dop     = (const float*)d_in[4];
    const float* W_i     = (const float*)d_in[5];
    const float* W_h     = (const float*)d_in[6];
    const float* W_o     = (const float*)d_in[7];
    const float* b_o     = (const float*)d_in[8];
    const int*   a2b     = (const int*)d_in[9];
    const int*   b2a     = (const int*)d_in[10];
    const int*   b2revb  = (const int*)d_in[11];
    float* out = (float*)d_out;

    float *inp, *msg, *tmp, *amsg, *ah;
    cudaGetSymbolAddress((void**)&inp,  g_inp);
    cudaGetSymbolAddress((void**)&msg,  g_msg);
    cudaGetSymbolAddress((void**)&tmp,  g_tmp);
    cudaGetSymbolAddress((void**)&amsg, g_amsg);
    cudaGetSymbolAddress((void**)&ah,   g_ah);

    dim3 blk(256);
    dim3 gridBonds((HIDDEN + TBN - 1) / TBN, (N_BONDS + TBM - 1) / TBM);   // (4, 1563)
    dim3 gridAtoms((HIDDEN + TBN - 1) / TBN, (N_ATOMS + TBM - 1) / TBM);   // (4, 782)
    dim3 vblk(80, 4);

    // inp = f_bonds @ W_i ; msg = relu(inp)
    tgemm300<<<gridBonds, blk>>>(f_bonds, BOND_FDIM, W_i, msg,
                                 nullptr, nullptr, inp, N_BONDS, BOND_FDIM, 1);

    for (int d = 0; d < DEPTH - 1; ++d) {
        gather_atoms4<<<(N_ATOMS + 3) / 4, vblk>>>(
            (const float4*)msg, w_bonds, a2b, (float4*)amsg);
        bond_update4<<<(N_BONDS + 3) / 4, vblk>>>(
            (const float4*)amsg, (const float4*)msg, w_bonds, b2a, b2revb, (float4*)tmp);
        // msg = relu(inp + tmp @ W_h)
        tgemm300<<<gridBonds, blk>>>(tmp, HIDDEN, W_h, msg,
                                     inp, nullptr, nullptr, N_BONDS, HIDDEN, 1);
    }

    gather_atoms4<<<(N_ATOMS + 3) / 4, vblk>>>(
        (const float4*)msg, w_bonds, a2b, (float4*)amsg);

    // ah = f_atoms @ W_o[0:133] + b_o   (no relu yet)
    tgemm300<<<gridAtoms, blk>>>(f_atoms, ATOM_FDIM, W_o, ah,
                                 nullptr, b_o, nullptr, N_ATOMS, ATOM_FDIM, 0);
    // ah = relu(ah + amsg @ W_o[133:433])
    tgemm300<<<gridAtoms, blk>>>(amsg, HIDDEN, W_o + (size_t)ATOM_FDIM * HIDDEN, ah,
                                 ah, nullptr, nullptr, N_ATOMS, HIDDEN, 1);

    readout4<<<(N_MOLS + 3) / 4, vblk>>>(
        (const float4*)ah, w_atoms, dop, (float4*)out);
}

// round 7
// speedup vs baseline: 1.8231x; 1.0452x over previous
#include <cuda_runtime.h>
#include <cstdint>

#define N_MOLS        2000
#define ATOMS_PER_MOL 50
#define N_ATOMS       (N_MOLS * ATOMS_PER_MOL + 1)   // 100001
#define N_BONDS       200001
#define MAX_NB        6
#define ATOM_FDIM     133
#define BOND_FDIM     147
#define HIDDEN        300
#define DEPTH         4
#define H4            (HIDDEN / 4)
#define FB_PAD        148    // f_bonds cols padded -> 592B rows (16B aligned)
#define FA_PAD        136    // f_atoms cols padded -> 544B rows (16B aligned)

// ---------------- persistent scratch (device globals; 16B aligned) ----------------
__device__ __align__(16) float g_inp [(size_t)N_BONDS * HIDDEN];
__device__ __align__(16) float g_msg [(size_t)N_BONDS * HIDDEN];
__device__ __align__(16) float g_tmp [(size_t)N_BONDS * HIDDEN];
__device__ __align__(16) float g_amsg[(size_t)N_ATOMS * HIDDEN];
__device__ __align__(16) float g_ah  [(size_t)N_ATOMS * HIDDEN];
__device__ __align__(16) float g_fbt [(size_t)N_BONDS * FB_PAD];          // tf32 f_bonds, padded
__device__ __align__(16) float g_fat [(size_t)N_ATOMS * FA_PAD];          // tf32 f_atoms, padded
__device__ __align__(16) float g_Wi  [BOND_FDIM * HIDDEN];                // tf32 weights
__device__ __align__(16) float g_Wh  [HIDDEN * HIDDEN];
__device__ __align__(16) float g_Wo  [(ATOM_FDIM + HIDDEN) * HIDDEN];

// ---------------- tf32 helpers ----------------
__device__ __forceinline__ uint32_t f2tf(float x) {
    uint32_t u;
    asm("cvt.rna.tf32.f32 %0, %1;" : "=r"(u) : "f"(x));
    return u;
}
__device__ __forceinline__ float f2tf_f(float x) { return __uint_as_float(f2tf(x)); }

__device__ __forceinline__ void mma_tf32(float* c, const uint32_t* a, const uint32_t* b) {
    asm volatile(
        "mma.sync.aligned.m16n8k8.row.col.f32.tf32.tf32.f32 "
        "{%0,%1,%2,%3}, {%4,%5,%6,%7}, {%8,%9}, {%0,%1,%2,%3};"
        : "+f"(c[0]), "+f"(c[1]), "+f"(c[2]), "+f"(c[3])
        : "r"(a[0]), "r"(a[1]), "r"(a[2]), "r"(a[3]), "r"(b[0]), "r"(b[1]));
}

// ---------------- pre-conversion kernels ----------------
__global__ void cvt_flat(const float* __restrict__ in, float* __restrict__ out, int n) {
    int i = blockIdx.x * blockDim.x + threadIdx.x;
    if (i < n) out[i] = f2tf_f(in[i]);
}
__global__ void cvt_pad(const float* __restrict__ in, float* __restrict__ out,
                        int n, int cin, int cout) {   // n = rows*cout
    int i = blockIdx.x * blockDim.x + threadIdx.x;
    if (i >= n) return;
    int r = i / cout, c = i - r * cout;
    out[i] = (c < cin) ? f2tf_f(in[(size_t)r * cin + c]) : 0.f;
}

// ---------------- pipelined tf32 tensor-core GEMM ----------------
// C[M,300] = relu?( A[M,K] @ B[K,300] (+ addsrc) (+ bias) ); optional pre-relu store.
// A and B must already hold tf32-rounded values; A rows 16B-aligned (lda*4 % 16 == 0).
#define TBM 128
#define TBN 160
#define TBK 16
#define STAGES 3
#define AST 20        // A smem k-stride (words): conflict-free fragment reads, 16B aligned
#define BST 168       // B smem n-stride (words): 168 % 32 == 8 -> conflict-free
#define A_WORDS (TBM * AST)   // 2560
#define B_WORDS (TBK * BST)   // 2688
#define SMEM_BYTES (STAGES * (A_WORDS + B_WORDS) * 4)   // 62976

__global__ __launch_bounds__(512) void tgemm300(
    const float* __restrict__ A, int lda,
    const float* __restrict__ B,          // [K,300] row-major (tf32 bits)
    float* __restrict__ C,
    const float* __restrict__ addsrc,
    const float* __restrict__ bias,
    float* __restrict__ rawout,
    int M, int K, int doRelu)
{
    extern __shared__ uint32_t sm[];
    uint32_t* sA = sm;                          // [STAGES][A_WORDS]
    uint32_t* sB = sm + STAGES * A_WORDS;       // [STAGES][B_WORDS]
    const uint32_t sAaddr = (uint32_t)__cvta_generic_to_shared(sA);
    const uint32_t sBaddr = (uint32_t)__cvta_generic_to_shared(sB);

    const int tid  = threadIdx.x;
    const int lane = tid & 31;
    const int warp = tid >> 5;          // 0..15
    const int g = lane >> 2;            // 0..7
    const int t = lane & 3;             // 0..3
    const int warpM = warp & 3;         // 4 warps along M
    const int warpN = warp >> 2;        // 4 warps along N
    const int m0w = warpM * 32;
    const int n0w = warpN * 40;

    const int rowBase = blockIdx.y * TBM;
    const int colBase = blockIdx.x * TBN;

    // A copy role: one 16B chunk per thread: row am, k-offset ak
    const int am = tid >> 2;                 // 0..127
    const int ak = (tid & 3) * 4;            // 0,4,8,12
    const int gr = rowBase + am;
    const float* aRow = A + (size_t)((gr < M) ? gr : 0) * lda;

    const int nCh = (K + TBK - 1) / TBK;

    auto issue = [&](int c) {
        const int stg = c % STAGES;
        // --- A: 128 x 16 floats = 512 x 16B ---
        {
            int gk = c * TBK + ak;
            int by = (gr < M) ? (K - gk) * 4 : 0;
            by = by < 0 ? 0 : (by > 16 ? 16 : by);
            const float* src = by ? (aRow + gk) : A;
            uint32_t dst = sAaddr + (uint32_t)(stg * A_WORDS + am * AST + ak) * 4u;
            asm volatile("cp.async.ca.shared.global [%0], [%1], 16, %2;"
                         :: "r"(dst), "l"(src), "r"(by) : "memory");
        }
        // --- B: 16 x 160 floats = 640 x 16B ---
        #pragma unroll
        for (int it = 0; it < 2; it++) {
            int e = it * 512 + tid;
            if (it == 1 && tid >= 128) break;
            int bk  = e / 40;
            int bn4 = (e - bk * 40) * 4;
            int gk  = c * TBK + bk;
            int gn  = colBase + bn4;
            int by  = (gk < K) ? (HIDDEN - gn) * 4 : 0;
            by = by < 0 ? 0 : (by > 16 ? 16 : by);
            const float* src = by ? (B + (size_t)gk * HIDDEN + gn) : B;
            uint32_t dst = sBaddr + (uint32_t)(stg * B_WORDS + bk * BST + bn4) * 4u;
            asm volatile("cp.async.ca.shared.global [%0], [%1], 16, %2;"
                         :: "r"(dst), "l"(src), "r"(by) : "memory");
        }
    };

    float acc[2][5][4];
    #pragma unroll
    for (int i = 0; i < 2; i++)
        #pragma unroll
        for (int j = 0; j < 5; j++)
            #pragma unroll
            for (int q = 0; q < 4; q++) acc[i][j][q] = 0.f;

    // prologue: stages 0..STAGES-2
    #pragma unroll
    for (int s = 0; s < STAGES - 1; s++) {
        if (s < nCh) issue(s);
        asm volatile("cp.async.commit_group;" ::: "memory");
    }

    for (int c = 0; c < nCh; c++) {
        asm volatile("cp.async.wait_group %0;" :: "n"(STAGES - 2) : "memory");
        __syncthreads();
        const uint32_t* As = sA + (c % STAGES) * A_WORDS;
        const uint32_t* Bs = sB + (c % STAGES) * B_WORDS;

        #pragma unroll
        for (int ks = 0; ks < 2; ks++) {
            const int kk = ks * 8;
            uint32_t af[2][4];
            #pragma unroll
            for (int mt = 0; mt < 2; mt++) {
                int r = m0w + mt * 16;
                af[mt][0] = As[(r + g    ) * AST + kk + t    ];
                af[mt][1] = As[(r + g + 8) * AST + kk + t    ];
                af[mt][2] = As[(r + g    ) * AST + kk + t + 4];
                af[mt][3] = As[(r + g + 8) * AST + kk + t + 4];
            }
            uint32_t bf[5][2];
            #pragma unroll
            for (int nt = 0; nt < 5; nt++) {
                int nc = n0w + nt * 8 + g;
                bf[nt][0] = Bs[(kk + t    ) * BST + nc];
                bf[nt][1] = Bs[(kk + t + 4) * BST + nc];
            }
            #pragma unroll
            for (int mt = 0; mt < 2; mt++)
                #pragma unroll
                for (int nt = 0; nt < 5; nt++)
                    mma_tf32(acc[mt][nt], af[mt], bf[nt]);
        }
        // stage (c+2)%STAGES held chunk c-1, finished by all warps before this
        // iteration's __syncthreads -> safe to overwrite without a second barrier.
        int nx = c + STAGES - 1;
        if (nx < nCh) issue(nx);
        asm volatile("cp.async.commit_group;" ::: "memory");
    }

    // epilogue
    #pragma unroll
    for (int mt = 0; mt < 2; mt++) {
        int r0 = rowBase + m0w + mt * 16 + g;
        int r1 = r0 + 8;
        #pragma unroll
        for (int nt = 0; nt < 5; nt++) {
            int c0 = colBase + n0w + nt * 8 + t * 2;
            #pragma unroll
            for (int q = 0; q < 4; q++) {
                int row = (q < 2) ? r0 : r1;
                int col = c0 + (q & 1);
                if (row >= M || col >= HIDDEN) continue;
                float v = acc[mt][nt][q];
                if (bias)   v += bias[col];
                if (addsrc) v += addsrc[(size_t)row * HIDDEN + col];
                if (rawout) rawout[(size_t)row * HIDDEN + col] = v;
                C[(size_t)row * HIDDEN + col] = doRelu ? fmaxf(v, 0.f) : v;
            }
        }
    }
}

// ---------------- atom aggregation (float4) ----------------
__global__ __launch_bounds__(320) void gather_atoms4(
    const float4* __restrict__ msg4, const float* __restrict__ w_bonds,
    const int* __restrict__ a2b, float4* __restrict__ amsg4, int doRound)
{
    const int tx = threadIdx.x;        // 0..79
    const int ty = threadIdx.y;        // 0..3
    const int a  = blockIdx.x * 4 + ty;
    __shared__ int   sb[4][MAX_NB];
    __shared__ float sw[4][MAX_NB];
    if (a < N_ATOMS && tx < MAX_NB) {
        int b = a2b[(size_t)a * MAX_NB + tx];
        sb[ty][tx] = b;
        sw[ty][tx] = w_bonds[b];
    }
    __syncthreads();
    if (a < N_ATOMS && tx < H4) {
        float4 acc = make_float4(0.f, 0.f, 0.f, 0.f);
        #pragma unroll
        for (int k = 0; k < MAX_NB; k++) {
            float  w = sw[ty][k];
            float4 v = msg4[(size_t)sb[ty][k] * H4 + tx];
            acc.x = fmaf(w, v.x, acc.x);
            acc.y = fmaf(w, v.y, acc.y);
            acc.z = fmaf(w, v.z, acc.z);
            acc.w = fmaf(w, v.w, acc.w);
        }
        if (doRound) {   // last gather feeds the GEMM as the A operand
            acc.x = f2tf_f(acc.x); acc.y = f2tf_f(acc.y);
            acc.z = f2tf_f(acc.z); acc.w = f2tf_f(acc.w);
        }
        amsg4[(size_t)a * H4 + tx] = acc;
    }
}

// ---------------- bond update (float4), emits tf32-rounded values ----------------
__global__ __launch_bounds__(320) void bond_update4(
    const float4* __restrict__ amsg4, const float4* __restrict__ msg4,
    const float* __restrict__ w_bonds,
    const int* __restrict__ b2a, const int* __restrict__ b2revb,
    float4* __restrict__ tmp4)
{
    const int tx = threadIdx.x;
    const int ty = threadIdx.y;
    const int b  = blockIdx.x * 4 + ty;
    __shared__ int   sa[4], srb[4];
    __shared__ float sw[4];
    if (b < N_BONDS && tx == 0) { sa[ty] = b2a[b]; srb[ty] = b2revb[b]; sw[ty] = w_bonds[b]; }
    __syncthreads();
    if (b < N_BONDS && tx < H4) {
        float4 am = amsg4[(size_t)sa[ty]  * H4 + tx];
        float4 mv = msg4 [(size_t)srb[ty] * H4 + tx];
        float  w  = sw[ty];
        float4 o;
        o.x = f2tf_f(am.x - w * mv.x);
        o.y = f2tf_f(am.y - w * mv.y);
        o.z = f2tf_f(am.z - w * mv.z);
        o.w = f2tf_f(am.w - w * mv.w);
        tmp4[(size_t)b * H4 + tx] = o;
    }
}

// ---------------- readout (float4) ----------------
__global__ __launch_bounds__(320) void readout4(
    const float4* __restrict__ ah4, const float* __restrict__ w_atoms,
    const float* __restrict__ dop, float4* __restrict__ out4)
{
    const int tx = threadIdx.x;
    const int ty = threadIdx.y;
    const int m  = blockIdx.x * 4 + ty;
    if (m >= N_MOLS || tx >= H4) return;
    const int base = 1 + m * ATOMS_PER_MOL;
    float4 s = make_float4(0.f, 0.f, 0.f, 0.f);
    float ws = 0.f;
    #pragma unroll 5
    for (int i = 0; i < ATOMS_PER_MOL; i++) {
        float  w = w_atoms[base + i];
        float4 v = ah4[(size_t)(base + i) * H4 + tx];
        ws += w;
        s.x = fmaf(w, v.x, s.x);
        s.y = fmaf(w, v.y, s.y);
        s.z = fmaf(w, v.z, s.z);
        s.w = fmaf(w, v.w, s.w);
    }
    float sc = dop[m] / ws;
    s.x *= sc; s.y *= sc; s.z *= sc; s.w *= sc;
    out4[(size_t)m * H4 + tx] = s;
}

// ---------------- launch ----------------
extern "C" void kernel_launch(void* const* d_in, const int* in_sizes, int n_in,
                              void* d_out, int out_size)
{
    const float* f_atoms = (const float*)d_in[0];
    const float* f_bonds = (const float*)d_in[1];
    const float* w_atoms = (const float*)d_in[2];
    const float* w_bonds = (const float*)d_in[3];
    const float* dop     = (const float*)d_in[4];
    const float* W_i     = (const float*)d_in[5];
    const float* W_h     = (const float*)d_in[6];
    const float* W_o     = (const float*)d_in[7];
    const float* b_o     = (const float*)d_in[8];
    const int*   a2b     = (const int*)d_in[9];
    const int*   b2a     = (const int*)d_in[10];
    const int*   b2revb  = (const int*)d_in[11];
    float* out = (float*)d_out;

    float *inp, *msg, *tmp, *amsg, *ah, *fbt, *fat, *Wi, *Wh, *Wo;
    cudaGetSymbolAddress((void**)&inp,  g_inp);
    cudaGetSymbolAddress((void**)&msg,  g_msg);
    cudaGetSymbolAddress((void**)&tmp,  g_tmp);
    cudaGetSymbolAddress((void**)&amsg, g_amsg);
    cudaGetSymbolAddress((void**)&ah,   g_ah);
    cudaGetSymbolAddress((void**)&fbt,  g_fbt);
    cudaGetSymbolAddress((void**)&fat,  g_fat);
    cudaGetSymbolAddress((void**)&Wi,   g_Wi);
    cudaGetSymbolAddress((void**)&Wh,   g_Wh);
    cudaGetSymbolAddress((void**)&Wo,   g_Wo);

    cudaFuncSetAttribute(tgemm300, cudaFuncAttributeMaxDynamicSharedMemorySize, SMEM_BYTES);

    dim3 blk(512);
    dim3 gridBonds((HIDDEN + TBN - 1) / TBN, (N_BONDS + TBM - 1) / TBM);   // (2, 1563)
    dim3 gridAtoms((HIDDEN + TBN - 1) / TBN, (N_ATOMS + TBM - 1) / TBM);   // (2, 782)
    dim3 vblk(80, 4);

    // pre-round everything the GEMM consumes
    {
        int n;
        n = N_BONDS * FB_PAD;
        cvt_pad <<<(n + 255) / 256, 256>>>(f_bonds, fbt, n, BOND_FDIM, FB_PAD);
        n = N_ATOMS * FA_PAD;
        cvt_pad <<<(n + 255) / 256, 256>>>(f_atoms, fat, n, ATOM_FDIM, FA_PAD);
        n = BOND_FDIM * HIDDEN;
        cvt_flat<<<(n + 255) / 256, 256>>>(W_i, Wi, n);
        n = HIDDEN * HIDDEN;
        cvt_flat<<<(n + 255) / 256, 256>>>(W_h, Wh, n);
        n = (ATOM_FDIM + HIDDEN) * HIDDEN;
        cvt_flat<<<(n + 255) / 256, 256>>>(W_o, Wo, n);
    }

    // inp = f_bonds @ W_i ; msg = relu(inp)
    tgemm300<<<gridBonds, blk, SMEM_BYTES>>>(fbt, FB_PAD, Wi, msg,
                                             nullptr, nullptr, inp, N_BONDS, BOND_FDIM, 1);

    for (int d = 0; d < DEPTH - 1; ++d) {
        gather_atoms4<<<(N_ATOMS + 3) / 4, vblk>>>(
            (const float4*)msg, w_bonds, a2b, (float4*)amsg, 0);
        bond_update4<<<(N_BONDS + 3) / 4, vblk>>>(
            (const float4*)amsg, (const float4*)msg, w_bonds, b2a, b2revb, (float4*)tmp);
        // msg = relu(inp + tmp @ W_h)
        tgemm300<<<gridBonds, blk, SMEM_BYTES>>>(tmp, HIDDEN, Wh, msg,
                                                 inp, nullptr, nullptr, N_BONDS, HIDDEN, 1);
    }

    gather_atoms4<<<(N_ATOMS + 3) / 4, vblk>>>(
        (const float4*)msg, w_bonds, a2b, (float4*)amsg, 1);   // rounded: GEMM A operand

    // ah = amsg @ W_o[133:433] + b_o   (no relu yet)
    tgemm300<<<gridAtoms, blk, SMEM_BYTES>>>(amsg, HIDDEN, Wo + (size_t)ATOM_FDIM * HIDDEN, ah,
                                             nullptr, b_o, nullptr, N_ATOMS, HIDDEN, 0);
    // ah = relu(ah + f_atoms @ W_o[0:133])
    tgemm300<<<gridAtoms, blk, SMEM_BYTES>>>(fat, FA_PAD, Wo, ah,
                                             ah, nullptr, nullptr, N_ATOMS, ATOM_FDIM, 1);

    readout4<<<(N_MOLS + 3) / 4, vblk>>>(
        (const float4*)ah, w_atoms, dop, (float4*)out);
}

// round 8
// speedup vs baseline: 2.4340x; 1.3351x over previous
#include <cuda_runtime.h>
#include <cstdint>

#define N_MOLS        2000
#define ATOMS_PER_MOL 50
#define N_ATOMS       (N_MOLS * ATOMS_PER_MOL + 1)   // 100001
#define N_BONDS       200001
#define MAX_NB        6
#define ATOM_FDIM     133
#define BOND_FDIM     147
#define HIDDEN        300
#define DEPTH         4
#define H4            (HIDDEN / 4)
#define FB_PAD        148                    // f_bonds cols padded (16B rows)
#define CAT_K         436                    // 300 (amsg) + 133 (f_atoms) + 3 pad
#define CAT4          (CAT_K / 4)            // 109

// ---------------- persistent scratch (device globals; 16B aligned) ----------------
__device__ __align__(16) float g_inp [(size_t)N_BONDS * HIDDEN];
__device__ __align__(16) float g_msg [(size_t)N_BONDS * HIDDEN];
__device__ __align__(16) float g_tmp [(size_t)N_BONDS * HIDDEN];
__device__ __align__(16) float g_amsg[(size_t)N_ATOMS * HIDDEN];
__device__ __align__(16) float g_ah  [(size_t)N_ATOMS * HIDDEN];
__device__ __align__(16) float g_fbt [(size_t)N_BONDS * FB_PAD];    // tf32 f_bonds, padded
__device__ __align__(16) float g_cat [(size_t)N_ATOMS * CAT_K];     // [amsg | tf32 f_atoms | 0]
__device__ __align__(16) float g_Wi  [BOND_FDIM * HIDDEN];          // tf32 weights
__device__ __align__(16) float g_Wh  [HIDDEN * HIDDEN];
__device__ __align__(16) float g_WoC [CAT_K * HIDDEN];              // W_o rows permuted to cat order

// ---------------- tf32 helpers ----------------
__device__ __forceinline__ uint32_t f2tf(float x) {
    uint32_t u;
    asm("cvt.rna.tf32.f32 %0, %1;" : "=r"(u) : "f"(x));
    return u;
}
__device__ __forceinline__ float f2tf_f(float x) { return __uint_as_float(f2tf(x)); }

__device__ __forceinline__ void mma_tf32(float* c, const uint32_t* a, const uint32_t* b) {
    asm volatile(
        "mma.sync.aligned.m16n8k8.row.col.f32.tf32.tf32.f32 "
        "{%0,%1,%2,%3}, {%4,%5,%6,%7}, {%8,%9}, {%0,%1,%2,%3};"
        : "+f"(c[0]), "+f"(c[1]), "+f"(c[2]), "+f"(c[3])
        : "r"(a[0]), "r"(a[1]), "r"(a[2]), "r"(a[3]), "r"(b[0]), "r"(b[1]));
}

// ---------------- pre-conversion kernels ----------------
__global__ void cvt_flat(const float* __restrict__ in, float* __restrict__ out, int n) {
    int i = blockIdx.x * blockDim.x + threadIdx.x;
    if (i < n) out[i] = f2tf_f(in[i]);
}
__global__ void cvt_pad(const float* __restrict__ in, float* __restrict__ out,
                        int n, int cin, int cout) {
    int i = blockIdx.x * blockDim.x + threadIdx.x;
    if (i >= n) return;
    int r = i / cout, c = i - r * cout;
    out[i] = (c < cin) ? f2tf_f(in[(size_t)r * cin + c]) : 0.f;
}
// fill cat cols [300, 436): tf32 f_atoms then zero pad
__global__ void cvt_cat_atoms(const float* __restrict__ fa, float* __restrict__ cat, int n) {
    int i = blockIdx.x * blockDim.x + threadIdx.x;   // n = N_ATOMS * 136
    if (i >= n) return;
    int r = i / 136, c = i - r * 136;
    cat[(size_t)r * CAT_K + HIDDEN + c] =
        (c < ATOM_FDIM) ? f2tf_f(fa[(size_t)r * ATOM_FDIM + c]) : 0.f;
}
// WoC[k'][n]: k'<300 -> W_o[133+k'], k'<433 -> W_o[k'-300], else 0
__global__ void cvt_wo_cat(const float* __restrict__ Wo, float* __restrict__ WoC, int n) {
    int i = blockIdx.x * blockDim.x + threadIdx.x;   // n = CAT_K * 300
    if (i >= n) return;
    int kp = i / HIDDEN, c = i - kp * HIDDEN;
    float v = 0.f;
    if (kp < HIDDEN)            v = Wo[(size_t)(ATOM_FDIM + kp) * HIDDEN + c];
    else if (kp < HIDDEN + ATOM_FDIM) v = Wo[(size_t)(kp - HIDDEN) * HIDDEN + c];
    WoC[i] = f2tf_f(v);
}

// ---------------- pipelined tf32 tensor-core GEMM, 64x40 warp tiles ----------------
// C[M,300] = relu?( A[M,K] @ B[K,300] (+ addsrc) (+ bias) ); optional pre-relu store.
#define TBM 128
#define TBN 160
#define TBK 16
#define STAGES 4
#define AST 20        // A smem k-stride (words): conflict-free, 16B aligned
#define BST 168       // B smem n-stride (words): 168 % 32 == 8 -> conflict-free
#define A_WORDS (TBM * AST)   // 2560
#define B_WORDS (TBK * BST)   // 2688
#define SMEM_BYTES (STAGES * (A_WORDS + B_WORDS) * 4)   // 83968

__global__ __launch_bounds__(256, 2) void tgemm300(
    const float* __restrict__ A, int lda,
    const float* __restrict__ B,
    float* __restrict__ C,
    const float* __restrict__ addsrc,
    const float* __restrict__ bias,
    float* __restrict__ rawout,
    int M, int K, int doRelu)
{
    extern __shared__ uint32_t sm[];
    uint32_t* sA = sm;
    uint32_t* sB = sm + STAGES * A_WORDS;
    const uint32_t sAaddr = (uint32_t)__cvta_generic_to_shared(sA);
    const uint32_t sBaddr = (uint32_t)__cvta_generic_to_shared(sB);

    const int tid  = threadIdx.x;
    const int lane = tid & 31;
    const int warp = tid >> 5;          // 0..7
    const int g = lane >> 2;
    const int t = lane & 3;
    const int m0w = (warp & 1) * 64;    // 2 warps along M
    const int n0w = (warp >> 1) * 40;   // 4 warps along N

    const int rowBase = blockIdx.y * TBM;
    const int colBase = blockIdx.x * TBN;
    const int nCh = (K + TBK - 1) / TBK;

    auto issue = [&](int c) {
        const int stg = c % STAGES;
        // A: 128 rows x 16 k = 512 x 16B, 2 chunks/thread
        #pragma unroll
        for (int it = 0; it < 2; it++) {
            int e    = it * 256 + tid;
            int row  = e >> 2;
            int koff = (e & 3) * 4;
            int gr   = rowBase + row;
            int gk   = c * TBK + koff;
            int by   = (gr < M) ? (K - gk) * 4 : 0;
            by = by < 0 ? 0 : (by > 16 ? 16 : by);
            const float* src = by ? (A + (size_t)gr * lda + gk) : A;
            uint32_t dst = sAaddr + (uint32_t)(stg * A_WORDS + row * AST + koff) * 4u;
            asm volatile("cp.async.ca.shared.global [%0], [%1], 16, %2;"
                         :: "r"(dst), "l"(src), "r"(by) : "memory");
        }
        // B: 16 k x 160 n = 640 x 16B
        #pragma unroll
        for (int it = 0; it < 3; it++) {
            int e = it * 256 + tid;
            if (it == 2 && tid >= 128) break;
            int bk  = e / 40;
            int bn4 = (e - bk * 40) * 4;
            int gk  = c * TBK + bk;
            int gn  = colBase + bn4;
            int by  = (gk < K) ? (HIDDEN - gn) * 4 : 0;
            by = by < 0 ? 0 : (by > 16 ? 16 : by);
            const float* src = by ? (B + (size_t)gk * HIDDEN + gn) : B;
            uint32_t dst = sBaddr + (uint32_t)(stg * B_WORDS + bk * BST + bn4) * 4u;
            asm volatile("cp.async.ca.shared.global [%0], [%1], 16, %2;"
                         :: "r"(dst), "l"(src), "r"(by) : "memory");
        }
    };

    float acc[4][5][4];
    #pragma unroll
    for (int i = 0; i < 4; i++)
        #pragma unroll
        for (int j = 0; j < 5; j++)
            #pragma unroll
            for (int q = 0; q < 4; q++) acc[i][j][q] = 0.f;

    #pragma unroll
    for (int s = 0; s < STAGES - 1; s++) {
        if (s < nCh) issue(s);
        asm volatile("cp.async.commit_group;" ::: "memory");
    }

    for (int c = 0; c < nCh; c++) {
        asm volatile("cp.async.wait_group %0;" :: "n"(STAGES - 2) : "memory");
        __syncthreads();
        const uint32_t* As = sA + (c % STAGES) * A_WORDS;
        const uint32_t* Bs = sB + (c % STAGES) * B_WORDS;

        #pragma unroll
        for (int ks = 0; ks < 2; ks++) {
            const int kk = ks * 8;
            uint32_t af[4][4];
            #pragma unroll
            for (int mt = 0; mt < 4; mt++) {
                int r = m0w + mt * 16;
                af[mt][0] = As[(r + g    ) * AST + kk + t    ];
                af[mt][1] = As[(r + g + 8) * AST + kk + t    ];
                af[mt][2] = As[(r + g    ) * AST + kk + t + 4];
                af[mt][3] = As[(r + g + 8) * AST + kk + t + 4];
            }
            uint32_t bf[5][2];
            #pragma unroll
            for (int nt = 0; nt < 5; nt++) {
                int nc = n0w + nt * 8 + g;
                bf[nt][0] = Bs[(kk + t    ) * BST + nc];
                bf[nt][1] = Bs[(kk + t + 4) * BST + nc];
            }
            #pragma unroll
            for (int mt = 0; mt < 4; mt++)
                #pragma unroll
                for (int nt = 0; nt < 5; nt++)
                    mma_tf32(acc[mt][nt], af[mt], bf[nt]);
        }
        int nx = c + STAGES - 1;
        if (nx < nCh) issue(nx);
        asm volatile("cp.async.commit_group;" ::: "memory");
    }

    // epilogue (float2 stores; col pairs never straddle the N=300 edge)
    #pragma unroll
    for (int mt = 0; mt < 4; mt++) {
        #pragma unroll
        for (int half = 0; half < 2; half++) {
            int row = rowBase + m0w + mt * 16 + g + half * 8;
            if (row >= M) continue;
            #pragma unroll
            for (int nt = 0; nt < 5; nt++) {
                int col = colBase + n0w + nt * 8 + t * 2;
                if (col >= HIDDEN) continue;
                float vx = acc[mt][nt][half * 2 + 0];
                float vy = acc[mt][nt][half * 2 + 1];
                if (bias)   { vx += bias[col]; vy += bias[col + 1]; }
                if (addsrc) {
                    float2 a = *reinterpret_cast<const float2*>(addsrc + (size_t)row * HIDDEN + col);
                    vx += a.x; vy += a.y;
                }
                if (rawout) {
                    float2 r; r.x = vx; r.y = vy;
                    *reinterpret_cast<float2*>(rawout + (size_t)row * HIDDEN + col) = r;
                }
                if (doRelu) { vx = fmaxf(vx, 0.f); vy = fmaxf(vy, 0.f); }
                float2 o; o.x = vx; o.y = vy;
                *reinterpret_cast<float2*>(C + (size_t)row * HIDDEN + col) = o;
            }
        }
    }
}

// ---------------- atom aggregation (float4); optional tf32 round + arbitrary out stride ----------------
__global__ __launch_bounds__(320) void gather_atoms4(
    const float4* __restrict__ msg4, const float* __restrict__ w_bonds,
    const int* __restrict__ a2b, float4* __restrict__ out4, int outStride4, int doRound)
{
    const int tx = threadIdx.x;        // 0..79
    const int ty = threadIdx.y;        // 0..3
    const int a  = blockIdx.x * 4 + ty;
    __shared__ int   sb[4][MAX_NB];
    __shared__ float sw[4][MAX_NB];
    if (a < N_ATOMS && tx < MAX_NB) {
        int b = a2b[(size_t)a * MAX_NB + tx];
        sb[ty][tx] = b;
        sw[ty][tx] = w_bonds[b];
    }
    __syncthreads();
    if (a < N_ATOMS && tx < H4) {
        float4 acc = make_float4(0.f, 0.f, 0.f, 0.f);
        #pragma unroll
        for (int k = 0; k < MAX_NB; k++) {
            float  w = sw[ty][k];
            float4 v = msg4[(size_t)sb[ty][k] * H4 + tx];
            acc.x = fmaf(w, v.x, acc.x);
            acc.y = fmaf(w, v.y, acc.y);
            acc.z = fmaf(w, v.z, acc.z);
            acc.w = fmaf(w, v.w, acc.w);
        }
        if (doRound) {
            acc.x = f2tf_f(acc.x); acc.y = f2tf_f(acc.y);
            acc.z = f2tf_f(acc.z); acc.w = f2tf_f(acc.w);
        }
        out4[(size_t)a * outStride4 + tx] = acc;
    }
}

// ---------------- bond update (float4), emits tf32-rounded values ----------------
__global__ __launch_bounds__(320) void bond_update4(
    const float4* __restrict__ amsg4, const float4* __restrict__ msg4,
    const float* __restrict__ w_bonds,
    const int* __restrict__ b2a, const int* __restrict__ b2revb,
    float4* __restrict__ tmp4)
{
    const int tx = threadIdx.x;
    const int ty = threadIdx.y;
    const int b  = blockIdx.x * 4 + ty;
    __shared__ int   sa[4], srb[4];
    __shared__ float sw[4];
    if (b < N_BONDS && tx == 0) { sa[ty] = b2a[b]; srb[ty] = b2revb[b]; sw[ty] = w_bonds[b]; }
    __syncthreads();
    if (b < N_BONDS && tx < H4) {
        float4 am = amsg4[(size_t)sa[ty]  * H4 + tx];
        float4 mv = msg4 [(size_t)srb[ty] * H4 + tx];
        float  w  = sw[ty];
        float4 o;
        o.x = f2tf_f(am.x - w * mv.x);
        o.y = f2tf_f(am.y - w * mv.y);
        o.z = f2tf_f(am.z - w * mv.z);
        o.w = f2tf_f(am.w - w * mv.w);
        tmp4[(size_t)b * H4 + tx] = o;
    }
}

// ---------------- readout (float4) ----------------
__global__ __launch_bounds__(320) void readout4(
    const float4* __restrict__ ah4, const float* __restrict__ w_atoms,
    const float* __restrict__ dop, float4* __restrict__ out4)
{
    const int tx = threadIdx.x;
    const int ty = threadIdx.y;
    const int m  = blockIdx.x * 4 + ty;
    if (m >= N_MOLS || tx >= H4) return;
    const int base = 1 + m * ATOMS_PER_MOL;
    float4 s = make_float4(0.f, 0.f, 0.f, 0.f);
    float ws = 0.f;
    #pragma unroll 5
    for (int i = 0; i < ATOMS_PER_MOL; i++) {
        float  w = w_atoms[base + i];
        float4 v = ah4[(size_t)(base + i) * H4 + tx];
        ws += w;
        s.x = fmaf(w, v.x, s.x);
        s.y = fmaf(w, v.y, s.y);
        s.z = fmaf(w, v.z, s.z);
        s.w = fmaf(w, v.w, s.w);
    }
    float sc = dop[m] / ws;
    s.x *= sc; s.y *= sc; s.z *= sc; s.w *= sc;
    out4[(size_t)m * H4 + tx] = s;
}

// ---------------- launch ----------------
extern "C" void kernel_launch(void* const* d_in, const int* in_sizes, int n_in,
                              void* d_out, int out_size)
{
    const float* f_atoms = (const float*)d_in[0];
    const float* f_bonds = (const float*)d_in[1];
    const float* w_atoms = (const float*)d_in[2];
    const float* w_bonds = (const float*)d_in[3];
    const float* dop     = (const float*)d_in[4];
    const float* W_i     = (const float*)d_in[5];
    const float* W_h     = (const float*)d_in[6];
    const float* W_o     = (const float*)d_in[7];
    const float* b_o     = (const float*)d_in[8];
    const int*   a2b     = (const int*)d_in[9];
    const int*   b2a     = (const int*)d_in[10];
    const int*   b2revb  = (const int*)d_in[11];
    float* out = (float*)d_out;

    float *inp, *msg, *tmp, *amsg, *ah, *fbt, *cat, *Wi, *Wh, *WoC;
    cudaGetSymbolAddress((void**)&inp,  g_inp);
    cudaGetSymbolAddress((void**)&msg,  g_msg);
    cudaGetSymbolAddress((void**)&tmp,  g_tmp);
    cudaGetSymbolAddress((void**)&amsg, g_amsg);
    cudaGetSymbolAddress((void**)&ah,   g_ah);
    cudaGetSymbolAddress((void**)&fbt,  g_fbt);
    cudaGetSymbolAddress((void**)&cat,  g_cat);
    cudaGetSymbolAddress((void**)&Wi,   g_Wi);
    cudaGetSymbolAddress((void**)&Wh,   g_Wh);
    cudaGetSymbolAddress((void**)&WoC,  g_WoC);

    cudaFuncSetAttribute(tgemm300, cudaFuncAttributeMaxDynamicSharedMemorySize, SMEM_BYTES);

    dim3 blk(256);
    dim3 gridBonds((HIDDEN + TBN - 1) / TBN, (N_BONDS + TBM - 1) / TBM);   // (2, 1563)
    dim3 gridAtoms((HIDDEN + TBN - 1) / TBN, (N_ATOMS + TBM - 1) / TBM);   // (2, 782)
    dim3 vblk(80, 4);

    // pre-round / reshape everything the GEMMs consume
    {
        int n;
        n = N_BONDS * FB_PAD;
        cvt_pad     <<<(n + 255) / 256, 256>>>(f_bonds, fbt, n, BOND_FDIM, FB_PAD);
        n = N_ATOMS * 136;
        cvt_cat_atoms<<<(n + 255) / 256, 256>>>(f_atoms, cat, n);
        n = BOND_FDIM * HIDDEN;
        cvt_flat    <<<(n + 255) / 256, 256>>>(W_i, Wi, n);
        n = HIDDEN * HIDDEN;
        cvt_flat    <<<(n + 255) / 256, 256>>>(W_h, Wh, n);
        n = CAT_K * HIDDEN;
        cvt_wo_cat  <<<(n + 255) / 256, 256>>>(W_o, WoC, n);
    }

    // inp = f_bonds @ W_i ; msg = relu(inp)
    tgemm300<<<gridBonds, blk, SMEM_BYTES>>>(fbt, FB_PAD, Wi, msg,
                                             nullptr, nullptr, inp, N_BONDS, BOND_FDIM, 1);

    for (int d = 0; d < DEPTH - 1; ++d) {
        gather_atoms4<<<(N_ATOMS + 3) / 4, vblk>>>(
            (const float4*)msg, w_bonds, a2b, (float4*)amsg, H4, 0);
        bond_update4<<<(N_BONDS + 3) / 4, vblk>>>(
            (const float4*)amsg, (const float4*)msg, w_bonds, b2a, b2revb, (float4*)tmp);
        // msg = relu(inp + tmp @ W_h)
        tgemm300<<<gridBonds, blk, SMEM_BYTES>>>(tmp, HIDDEN, Wh, msg,
                                                 inp, nullptr, nullptr, N_BONDS, HIDDEN, 1);
    }

    // final gather writes amsg (tf32-rounded) straight into cat cols [0,300)
    gather_atoms4<<<(N_ATOMS + 3) / 4, vblk>>>(
        (const float4*)msg, w_bonds, a2b, (float4*)cat, CAT4, 1);

    // ah = relu([amsg | f_atoms] @ WoC + b_o)   -- single fused K=436 GEMM
    tgemm300<<<gridAtoms, blk, SMEM_BYTES>>>(cat, CAT_K, WoC, ah,
                                             nullptr, b_o, nullptr, N_ATOMS, CAT_K, 1);

    readout4<<<(N_MOLS + 3) / 4, vblk>>>(
        (const float4*)ah, w_atoms, dop, (float4*)out);
}